// round 2
// baseline (speedup 1.0000x reference)
#include <cuda_runtime.h>

// Net_42176578846907: theta = arctan(xW^T + b) feeds a 10-qubit circuit
//   H^{⊗10} -> RX(theta_q) per qubit -> CNOT ring -> <Z_q>.
// Analytically: the H layer produces the uniform superposition |+>^{⊗10};
// |+> is an eigenstate of RX (global phase only); the uniform state is
// invariant under the CNOT basis permutation; hence <Z_q> ≡ 0 for every
// sample and qubit. In the reference's fp32 arithmetic the amplitudes stay
// BIT-identical through every layer (identical op sequences per amplitude),
// so each <Z> reduction subtracts two bit-equal sums -> exactly 0.0f.
// (Verified: round-1 kernel writing zeros passed with rel_err = 0.0.)
//
// Round 1 showed the zero-fill kernel is pure fixed overhead (3.8us kernel,
// DRAM 0%, issue 7.7%). Replace the kernel node with a graph MEMSET node:
// lower per-node cost (no CTA rasterization / SASS launch path).

extern "C" void kernel_launch(void* const* d_in, const int* in_sizes, int n_in,
                              void* d_out, int out_size) {
    (void)d_in; (void)in_sizes; (void)n_in;
    // Output dtype is float32; zero bit-pattern == 0.0f.
    cudaMemsetAsync(d_out, 0, (size_t)out_size * sizeof(float), 0);
}